// round 5
// baseline (speedup 1.0000x reference)
#include <cuda_runtime.h>
#include <math.h>
#include <limits.h>

#define NIMG 4
#define NPRI 3106
#define NCLS 20      // classes 1..20 (background excluded)
#define NTOT 21
#define NPAD 4096    // max pow2 bound for sort arrays
#define TOPK 200
#define CPAD 4096    // next pow2 >= NCLS*TOPK = 4000

#define MIN_SCORE 0.05f
#define MAX_OVERLAP 0.45f

#define NMS_NT 512
#define NWARPS (NMS_NT / 32)

// ---------------- device scratch (no allocations allowed) ----------------
__device__ float  g_cls[NIMG][NCLS][NPRI];      // class-major probs
__device__ float4 g_box[NIMG][NPRI];            // decoded boxes x1,y1,x2,y2
__device__ float  g_candScore[NIMG][NCLS][TOPK];
__device__ float4 g_candBox[NIMG][NCLS][TOPK];
__device__ int    g_candCnt[NIMG][NCLS];

// ---------------- kernel 1: softmax + box decode (thread per row) ----------------
__global__ void softmax_decode_kernel(const float* __restrict__ locs,
                                      const float* __restrict__ scores,
                                      const float* __restrict__ priors)
{
    int row = blockIdx.x * blockDim.x + threadIdx.x;
    if (row >= NIMG * NPRI) return;
    int img = row / NPRI;
    int p   = row - img * NPRI;

    const float* s = scores + (size_t)row * NTOT;
    float m = s[0];
    #pragma unroll
    for (int c = 1; c < NTOT; c++) m = fmaxf(m, s[c]);

    float e[NTOT];
    double dsum = 0.0;
    #pragma unroll
    for (int c = 0; c < NTOT; c++) {
        e[c] = (float)exp((double)(s[c] - m));   // precise exp, fast-math proof
        dsum += (double)e[c];
    }
    float fsum = (float)dsum;
    #pragma unroll
    for (int c = 1; c < NTOT; c++)
        g_cls[img][c - 1][p] = __fdiv_rn(e[c], fsum);

    const float* l  = locs + (size_t)row * 4;
    const float* pr = priors + (size_t)p * 4;
    float cx = __fdiv_rn(l[0] * pr[2], 10.0f) + pr[0];
    float cy = __fdiv_rn(l[1] * pr[3], 10.0f) + pr[1];
    float w  = (float)exp((double)__fdiv_rn(l[2], 5.0f)) * pr[2];
    float h  = (float)exp((double)__fdiv_rn(l[3], 5.0f)) * pr[3];
    float4 b;
    b.x = cx - __fdiv_rn(w, 2.0f);
    b.y = cy - __fdiv_rn(h, 2.0f);
    b.z = cx + __fdiv_rn(w, 2.0f);
    b.w = cy + __fdiv_rn(h, 2.0f);
    g_box[img][p] = b;
}

// IoU matching reference float semantics exactly
__device__ __forceinline__ float iou_f(float4 a, float4 b)
{
    float dx = fminf(a.z, b.z) - fmaxf(a.x, b.x);
    float dy = fminf(a.w, b.w) - fmaxf(a.y, b.y);
    float inter = fmaxf(dx, 0.0f) * fmaxf(dy, 0.0f);
    float aA = (a.z - a.x) * (a.w - a.y);
    float aB = (b.z - b.x) * (b.w - b.y);
    return __fdiv_rn(inter, aA + aB - inter);
}

// ---------------- kernel 2: per-(image,class) blocked greedy NMS ----------------
// Dynamic shared layout:
//   [0, 16384)            float skey[NPAD]
//   [16384, 32768)        int   sidx[NPAD]
//   [32768, 32768+49696)  float4 sbox[NPRI]
//   [82464, +3106)        uchar ssup[NPRI]
#define SMEM_NMS_BYTES 85632

__global__ void __launch_bounds__(NMS_NT, 1)
nms_kernel()
{
    extern __shared__ char sm[];
    float*         skey = (float*)(sm);
    int*           sidx = (int*)(sm + NPAD * 4);
    float4*        sbox = (float4*)(sm + NPAD * 8);
    unsigned char* ssup = (unsigned char*)(sm + NPAD * 8 + NPRI * 16);
    __shared__ int    s_wcnt[NWARPS];
    __shared__ int    s_cand[32];
    __shared__ float4 s_kbox[32];
    __shared__ int    s_mkept;
    __shared__ int    s_last;

    int img = blockIdx.x / NCLS;
    int c   = blockIdx.x % NCLS;
    int tid = threadIdx.x;
    int wid = tid >> 5;
    int lane = tid & 31;

    // ---- Phase A: stable compaction of valid entries (order-preserving) ----
    int base = 0;  // uniform across threads
    for (int bp = 0; bp < NPRI; bp += NMS_NT) {
        int p = bp + tid;
        float sc = (p < NPRI) ? g_cls[img][c][p] : 0.0f;
        bool ok = (p < NPRI) && (sc > MIN_SCORE);
        unsigned b = __ballot_sync(0xffffffffu, ok);
        if (lane == 0) s_wcnt[wid] = __popc(b);
        __syncthreads();
        int wpre = 0, wsum = 0;
        #pragma unroll
        for (int w = 0; w < NWARPS; w++) {
            int cnt = s_wcnt[w];
            if (w < wid) wpre += cnt;
            wsum += cnt;
        }
        int rank = base + wpre + __popc(b & ((1u << lane) - 1u));
        if (ok) { skey[rank] = sc; sidx[rank] = p; }
        base += wsum;
        __syncthreads();
    }
    int nvalid = base;

    int keptTotal = 0;

    if (nvalid > 0) {
        // pow2 pad
        int npow = 32;
        while (npow < nvalid) npow <<= 1;
        for (int t = nvalid + tid; t < npow; t += NMS_NT) {
            skey[t] = -INFINITY;
            sidx[t] = NPRI + t;
        }
        __syncthreads();

        // ---- Phase B: bitonic sort (score desc, index asc) ----
        for (int k = 2; k <= npow; k <<= 1) {
            for (int j = k >> 1; j > 0; j >>= 1) {
                for (int t = tid; t < npow; t += NMS_NT) {
                    int l = t ^ j;
                    if (l > t) {
                        float ka = skey[t], kb = skey[l];
                        int   ia = sidx[t], ib = sidx[l];
                        bool asc = ((t & k) == 0);
                        bool beforeBA = (kb > ka) || (kb == ka && ib < ia);
                        if (beforeBA == asc) {
                            skey[t] = kb; skey[l] = ka;
                            sidx[t] = ib; sidx[l] = ia;
                        }
                    }
                }
                __syncthreads();
            }
        }

        // ---- Phase C: gather boxes, clear suppression ----
        for (int i = tid; i < nvalid; i += NMS_NT) {
            sbox[i] = g_box[img][sidx[i]];
            ssup[i] = 0;
        }
        __syncthreads();

        // ---- Phase D: blocked greedy (exact) ----
        int cur = 0;
        while (cur < nvalid && keptTotal < TOPK) {
            // gather next <=32 unsuppressed candidates into s_cand
            int m_cur = 0;
            int scanpos = cur;
            while (true) {
                int j = scanpos + tid;
                bool ok = (j < nvalid) && (ssup[j] == 0);
                unsigned b = __ballot_sync(0xffffffffu, ok);
                if (lane == 0) s_wcnt[wid] = __popc(b);
                __syncthreads();
                int wpre = 0, wsum = 0;
                #pragma unroll
                for (int w = 0; w < NWARPS; w++) {
                    int cnt = s_wcnt[w];
                    if (w < wid) wpre += cnt;
                    wsum += cnt;
                }
                int rank = m_cur + wpre + __popc(b & ((1u << lane) - 1u));
                if (ok && rank < 32) s_cand[rank] = j;
                m_cur = min(32, m_cur + wsum);
                scanpos += NMS_NT;
                __syncthreads();
                if (m_cur >= 32 || scanpos >= nvalid) break;
            }
            if (m_cur == 0) break;   // all remaining suppressed

            // warp 0: resolve greedy inside the chunk (register/ballot only)
            if (tid < 32) {
                int m = m_cur;
                int ci = s_cand[(tid < m) ? tid : 0];
                float4 bj = sbox[ci];
                unsigned over = 0;
                for (int i = 0; i < m; i++) {
                    float bix = __shfl_sync(0xffffffffu, bj.x, i);
                    float biy = __shfl_sync(0xffffffffu, bj.y, i);
                    float biz = __shfl_sync(0xffffffffu, bj.z, i);
                    float biw = __shfl_sync(0xffffffffu, bj.w, i);
                    float4 bi = make_float4(bix, biy, biz, biw);
                    if (tid > i && iou_f(bi, bj) > MAX_OVERLAP) over |= 1u << i;
                }
                unsigned sup = 0, keptmask = 0;
                for (int i = 0; i < m; i++) {
                    unsigned row = __ballot_sync(0xffffffffu, (over >> i) & 1u);
                    unsigned ikept = ((sup >> i) & 1u) ^ 1u;
                    keptmask |= ikept << i;
                    sup |= ikept ? row : 0u;
                }
                bool mykept = (tid < m) && ((keptmask >> tid) & 1u);
                int myrank = __popc(keptmask & ((1u << tid) - 1u));
                if (mykept) {
                    int slot = keptTotal + myrank;
                    if (slot < TOPK) {
                        g_candScore[img][c][slot] = skey[ci];
                        g_candBox[img][c][slot]   = bj;
                    }
                    s_kbox[myrank] = bj;
                }
                if (tid < m) ssup[ci] = 1;   // processed (kept or suppressed)
                if (tid == 0) {
                    s_mkept = __popc(keptmask);
                    s_last  = s_cand[m - 1];
                }
            }
            __syncthreads();

            int nk = s_mkept;
            keptTotal += nk;
            cur = s_last + 1;
            if (keptTotal >= TOPK || cur >= nvalid) break;

            // one full suppression scan vs all kept-in-chunk boxes
            if (nk > 0) {
                for (int j = cur + tid; j < nvalid; j += NMS_NT) {
                    if (ssup[j]) continue;
                    float4 bj = sbox[j];
                    for (int k2 = 0; k2 < nk; k2++) {
                        if (iou_f(s_kbox[k2], bj) > MAX_OVERLAP) {
                            ssup[j] = 1;
                            break;
                        }
                    }
                }
            }
            __syncthreads();
        }
    }

    // pad unused candidate slots; publish kept count
    int kc = min(keptTotal, TOPK);
    for (int r = kc + tid; r < TOPK; r += NMS_NT)
        g_candScore[img][c][r] = -INFINITY;
    if (tid == 0) g_candCnt[img][c] = keptTotal;
}

// ---------------- kernel 3: per-image global top-200 ----------------
#define TK_NT 1024
__global__ void __launch_bounds__(TK_NT, 1)
topk_kernel(float* __restrict__ out)
{
    __shared__ float skey[CPAD];
    __shared__ int   sslot[CPAD];
    __shared__ int   s_total;

    int img = blockIdx.x;
    int tid = threadIdx.x;

    if (tid == 0) {
        int t = 0;
        for (int c = 0; c < NCLS; c++) t += g_candCnt[img][c];
        s_total = t;
    }

    for (int t = tid; t < CPAD; t += TK_NT) {
        float key = -INFINITY;
        if (t < NCLS * TOPK) {
            int c = t / TOPK, r = t - c * TOPK;
            key = g_candScore[img][c][r];      // -inf padded
        }
        skey[t]  = key;
        sslot[t] = t;
    }
    __syncthreads();

    for (int k = 2; k <= CPAD; k <<= 1) {
        for (int j = k >> 1; j > 0; j >>= 1) {
            #pragma unroll
            for (int it = 0; it < CPAD / TK_NT; it++) {
                int t = tid + it * TK_NT;
                int l = t ^ j;
                if (l > t) {
                    float ka = skey[t], kb = skey[l];
                    int   ia = sslot[t], ib = sslot[l];
                    bool asc = ((t & k) == 0);
                    bool beforeBA = (kb > ka) || (kb == ka && ib < ia);
                    if (beforeBA == asc) {
                        skey[t] = kb; skey[l] = ka;
                        sslot[t] = ib; sslot[l] = ia;
                    }
                }
            }
            __syncthreads();
        }
    }

    float* outBoxes  = out;                                     // [4,200,4]
    float* outLabels = out + NIMG * TOPK * 4;                   // [4,200]
    float* outScores = out + NIMG * TOPK * 4 + NIMG * TOPK;     // [4,200]
    float* outCount  = out + NIMG * TOPK * 4 + 2 * NIMG * TOPK; // [4]

    for (int k = tid; k < TOPK; k += TK_NT) {
        float sc = skey[k];
        bool has = (sc != -INFINITY);
        float4 b = make_float4(0.f, 0.f, 0.f, 0.f);
        int lab = 0;
        float scout = 0.f;
        if (has) {
            int slot = sslot[k];
            int c = slot / TOPK, r = slot - c * TOPK;
            b = g_candBox[img][c][r];
            lab = c + 1;
            scout = sc;
        }
        int basei = (img * TOPK + k) * 4;
        outBoxes[basei + 0] = b.x;
        outBoxes[basei + 1] = b.y;
        outBoxes[basei + 2] = b.z;
        outBoxes[basei + 3] = b.w;
        outLabels[img * TOPK + k] = (float)lab;
        outScores[img * TOPK + k] = scout;
    }
    __syncthreads();

    if (tid == 0) {
        int cnt = min(s_total, TOPK);
        if (cnt == 0) {
            int basei = img * TOPK * 4;
            outBoxes[basei + 0] = 0.0f;
            outBoxes[basei + 1] = 0.0f;
            outBoxes[basei + 2] = 1.0f;
            outBoxes[basei + 3] = 1.0f;
            cnt = 1;
        }
        outCount[img] = (float)cnt;
    }
}

// ---------------- launch ----------------
extern "C" void kernel_launch(void* const* d_in, const int* in_sizes, int n_in,
                              void* d_out, int out_size)
{
    const float* locs   = (const float*)d_in[0];  // (4,3106,4)
    const float* scores = (const float*)d_in[1];  // (4,3106,21)
    const float* priors = (const float*)d_in[2];  // (3106,4)
    float* out = (float*)d_out;

    static bool attr_set = false;
    if (!attr_set) {
        cudaFuncSetAttribute(nms_kernel,
                             cudaFuncAttributeMaxDynamicSharedMemorySize,
                             SMEM_NMS_BYTES);
        attr_set = true;
    }

    int rows = NIMG * NPRI;
    softmax_decode_kernel<<<(rows + 127) / 128, 128>>>(locs, scores, priors);
    nms_kernel<<<NIMG * NCLS, NMS_NT, SMEM_NMS_BYTES>>>();
    topk_kernel<<<NIMG, TK_NT>>>(out);
}

// round 6
// speedup vs baseline: 1.2727x; 1.2727x over previous
#include <cuda_runtime.h>
#include <math.h>
#include <limits.h>

#define NIMG 4
#define NPRI 3106
#define NCLS 20      // classes 1..20 (background excluded)
#define NTOT 21
#define NPAD 4096    // max pow2 bound for sort arrays
#define TOPK 200
#define CPAD 4096    // next pow2 >= NCLS*TOPK = 4000

#define MIN_SCORE 0.05f
#define MAX_OVERLAP 0.45f

#define NMS_NT 512
#define NWARPS (NMS_NT / 32)

// ---------------- device scratch (no allocations allowed) ----------------
__device__ float  g_cls[NIMG][NCLS][NPRI];      // class-major probs
__device__ float4 g_box[NIMG][NPRI];            // decoded boxes x1,y1,x2,y2
__device__ float  g_candScore[NIMG][NCLS][TOPK];
__device__ float4 g_candBox[NIMG][NCLS][TOPK];
__device__ int    g_candCnt[NIMG][NCLS];

// Fast double-precision exp (Cody-Waite + deg-12 Taylor, rel err ~2^-52).
// Bit-equivalent (after fp32 rounding) to libm exp(double) for our ranges,
// immune to fast-math (pure DFMA chain). x finite, x > -700.
__device__ __forceinline__ float exp_df(float xf)
{
    double x = (double)xf;
    float nf = rintf(xf * 1.4426950408889634f);
    double n = (double)nf;
    double r = fma(n, -0.6931471805599453, x);      // - n*ln2_hi
    r = fma(n, -2.3190468138462996e-17, r);         // - n*ln2_lo
    double p = 2.08767569878681e-09;                // 1/12!
    p = fma(p, r, 2.505210838544172e-08);           // 1/11!
    p = fma(p, r, 2.755731922398589e-07);           // 1/10!
    p = fma(p, r, 2.755731922398589e-06);           // 1/9!
    p = fma(p, r, 2.480158730158730e-05);           // 1/8!
    p = fma(p, r, 1.984126984126984e-04);           // 1/7!
    p = fma(p, r, 1.388888888888889e-03);           // 1/6!
    p = fma(p, r, 8.333333333333333e-03);           // 1/5!
    p = fma(p, r, 4.166666666666666e-02);           // 1/4!
    p = fma(p, r, 1.666666666666667e-01);           // 1/3!
    p = fma(p, r, 0.5);
    p = fma(p, r, 1.0);
    p = fma(p, r, 1.0);
    long long ni = (long long)nf;
    double sc = __longlong_as_double((ni + 1023LL) << 52);  // 2^n (n > -1022 here)
    return (float)(p * sc);
}

// ---------------- kernel 1: softmax + box decode (thread per row) ----------------
__global__ void softmax_decode_kernel(const float* __restrict__ locs,
                                      const float* __restrict__ scores,
                                      const float* __restrict__ priors)
{
    int row = blockIdx.x * blockDim.x + threadIdx.x;
    if (row >= NIMG * NPRI) return;
    int img = row / NPRI;
    int p   = row - img * NPRI;

    const float* s = scores + (size_t)row * NTOT;
    float m = s[0];
    #pragma unroll
    for (int c = 1; c < NTOT; c++) m = fmaxf(m, s[c]);

    float e[NTOT];
    double dsum = 0.0;
    #pragma unroll
    for (int c = 0; c < NTOT; c++) {
        e[c] = exp_df(s[c] - m);
        dsum += (double)e[c];
    }
    float fsum = (float)dsum;
    #pragma unroll
    for (int c = 1; c < NTOT; c++)
        g_cls[img][c - 1][p] = __fdiv_rn(e[c], fsum);

    const float* l  = locs + (size_t)row * 4;
    const float* pr = priors + (size_t)p * 4;
    float cx = __fdiv_rn(l[0] * pr[2], 10.0f) + pr[0];
    float cy = __fdiv_rn(l[1] * pr[3], 10.0f) + pr[1];
    float w  = exp_df(__fdiv_rn(l[2], 5.0f)) * pr[2];
    float h  = exp_df(__fdiv_rn(l[3], 5.0f)) * pr[3];
    float4 b;
    b.x = cx - __fdiv_rn(w, 2.0f);
    b.y = cy - __fdiv_rn(h, 2.0f);
    b.z = cx + __fdiv_rn(w, 2.0f);
    b.w = cy + __fdiv_rn(h, 2.0f);
    g_box[img][p] = b;
}

// IoU matching reference float semantics exactly
__device__ __forceinline__ float iou_f(float4 a, float4 b)
{
    float dx = fminf(a.z, b.z) - fmaxf(a.x, b.x);
    float dy = fminf(a.w, b.w) - fmaxf(a.y, b.y);
    float inter = fmaxf(dx, 0.0f) * fmaxf(dy, 0.0f);
    float aA = (a.z - a.x) * (a.w - a.y);
    float aB = (b.z - b.x) * (b.w - b.y);
    return __fdiv_rn(inter, aA + aB - inter);
}

// ---------------- kernel 2: per-(image,class) greedy NMS ----------------
// Dynamic shared layout:
//   [0, 16384)             float   skey[NPAD]
//   [16384, 32768)         int     sidx[NPAD]
//   [32768, 82464)         float4  sbox[NPRI]
//   [82464, 94888)         uint    omask[NPRI]
#define SMEM_NMS_BYTES 94976

__global__ void __launch_bounds__(NMS_NT, 1)
nms_kernel()
{
    extern __shared__ char sm[];
    float*        skey  = (float*)(sm);
    int*          sidx  = (int*)(sm + NPAD * 4);
    float4*       sbox  = (float4*)(sm + NPAD * 8);
    unsigned int* omask = (unsigned int*)(sm + NPAD * 8 + NPRI * 16);
    __shared__ int      s_wcnt[NWARPS];
    __shared__ unsigned s_keptmask;

    int img  = blockIdx.x / NCLS;
    int c    = blockIdx.x % NCLS;
    int tid  = threadIdx.x;
    int wid  = tid >> 5;
    int lane = tid & 31;
    unsigned lmask = (1u << lane) - 1u;

    // ---- Phase A: stable compaction of valid entries (order-preserving) ----
    int base = 0;
    for (int bp = 0; bp < NPRI; bp += NMS_NT) {
        int p = bp + tid;
        float sc = (p < NPRI) ? g_cls[img][c][p] : 0.0f;
        bool ok = (p < NPRI) && (sc > MIN_SCORE);
        unsigned b = __ballot_sync(0xffffffffu, ok);
        if (lane == 0) s_wcnt[wid] = __popc(b);
        __syncthreads();
        int wpre = 0, wsum = 0;
        #pragma unroll
        for (int w = 0; w < NWARPS; w++) {
            int cnt = s_wcnt[w];
            if (w < wid) wpre += cnt;
            wsum += cnt;
        }
        int rank = base + wpre + __popc(b & lmask);
        if (ok) { skey[rank] = sc; sidx[rank] = p; }
        base += wsum;
        __syncthreads();
    }
    int nvalid = base;

    int keptTotal = 0;

    if (nvalid > 0) {
        int npow = 32;
        while (npow < nvalid) npow <<= 1;
        for (int t = nvalid + tid; t < npow; t += NMS_NT) {
            skey[t] = -INFINITY;
            sidx[t] = NPRI + t;
        }
        __syncthreads();

        // ---- Phase B: bitonic sort (score desc, index asc) ----
        for (int k = 2; k <= npow; k <<= 1) {
            for (int j = k >> 1; j > 0; j >>= 1) {
                for (int t = tid; t < npow; t += NMS_NT) {
                    int l = t ^ j;
                    if (l > t) {
                        float ka = skey[t], kb = skey[l];
                        int   ia = sidx[t], ib = sidx[l];
                        bool asc = ((t & k) == 0);
                        bool beforeBA = (kb > ka) || (kb == ka && ib < ia);
                        if (beforeBA == asc) {
                            skey[t] = kb; skey[l] = ka;
                            sidx[t] = ib; sidx[l] = ia;
                        }
                    }
                }
                __syncthreads();
            }
        }

        // ---- Phase C: gather boxes for sorted valid positions ----
        for (int i = tid; i < nvalid; i += NMS_NT)
            sbox[i] = g_box[img][sidx[i]];
        __syncthreads();

        // ---- Phase D: chunked greedy with survivor compaction (exact) ----
        int nrem = nvalid;
        while (nrem > 0 && keptTotal < TOPK) {
            int m = min(32, nrem);

            if (wid == 0) {
                // resolve chunk [0, m) greedily within warp 0
                int ridx = (lane < m) ? lane : 0;
                float4 bown = sbox[ridx];
                unsigned over = 0;
                for (int j = 0; j < m; j++) {
                    float4 bj = sbox[j];          // LDS broadcast
                    if (j < lane && iou_f(bj, bown) > MAX_OVERLAP)
                        over |= 1u << j;
                }
                unsigned unres = (m == 32) ? 0xffffffffu : ((1u << m) - 1u);
                unsigned kept = 0;
                while (unres) {
                    int i = __ffs(unres) - 1;
                    kept |= 1u << i;
                    unsigned row = __ballot_sync(0xffffffffu, (over >> i) & 1u);
                    unres &= ~(row | (1u << i));
                }
                bool mykept = (lane < m) && ((kept >> lane) & 1u);
                int myrank = __popc(kept & lmask);
                if (mykept) {
                    int slot = keptTotal + myrank;
                    if (slot < TOPK) {
                        g_candScore[img][c][slot] = skey[lane];
                        g_candBox[img][c][slot]   = bown;
                    }
                }
                if (lane == 0) s_keptmask = kept;
            } else {
                // warps 1..15: per-survivor overlap mask vs chunk (concurrent)
                for (int j = m + (tid - 32); j < nrem; j += (NMS_NT - 32)) {
                    float4 bj = sbox[j];
                    unsigned om = 0;
                    for (int i = 0; i < m; i++) {
                        float4 bi = sbox[i];      // LDS broadcast
                        if (iou_f(bi, bj) > MAX_OVERLAP) om |= 1u << i;
                    }
                    omask[j] = om;
                }
            }
            __syncthreads();

            unsigned keptmask = s_keptmask;
            keptTotal += __popc(keptmask);
            if (keptTotal >= TOPK) break;
            if (nrem <= 32) { nrem = 0; break; }

            // compact survivors [m, nrem) with (omask & keptmask)==0 to front
            int newbase = 0;
            for (int start = m; start < nrem; start += NMS_NT) {
                int j = start + tid;
                bool ok = (j < nrem) && ((omask[j] & keptmask) == 0u);
                float key = 0.0f; float4 bx;
                if (ok) { key = skey[j]; bx = sbox[j]; }
                unsigned b = __ballot_sync(0xffffffffu, ok);
                if (lane == 0) s_wcnt[wid] = __popc(b);
                __syncthreads();      // also separates reads from writes
                int wpre = 0, wsum = 0;
                #pragma unroll
                for (int w = 0; w < NWARPS; w++) {
                    int cnt = s_wcnt[w];
                    if (w < wid) wpre += cnt;
                    wsum += cnt;
                }
                int rank = newbase + wpre + __popc(b & lmask);
                if (ok) { skey[rank] = key; sbox[rank] = bx; }
                newbase += wsum;
                __syncthreads();
            }
            nrem = newbase;
        }
    }

    // pad unused candidate slots; publish kept count
    int kc = min(keptTotal, TOPK);
    for (int r = kc + tid; r < TOPK; r += NMS_NT)
        g_candScore[img][c][r] = -INFINITY;
    if (tid == 0) g_candCnt[img][c] = keptTotal;
}

// ---------------- kernel 3: per-image global top-200 ----------------
#define TK_NT 1024
__global__ void __launch_bounds__(TK_NT, 1)
topk_kernel(float* __restrict__ out)
{
    __shared__ float skey[CPAD];
    __shared__ int   sslot[CPAD];
    __shared__ int   s_total;

    int img = blockIdx.x;
    int tid = threadIdx.x;

    if (tid == 0) {
        int t = 0;
        for (int c = 0; c < NCLS; c++) t += g_candCnt[img][c];
        s_total = t;
    }

    for (int t = tid; t < CPAD; t += TK_NT) {
        float key = -INFINITY;
        if (t < NCLS * TOPK) {
            int c = t / TOPK, r = t - c * TOPK;
            key = g_candScore[img][c][r];      // -inf padded
        }
        skey[t]  = key;
        sslot[t] = t;
    }
    __syncthreads();

    for (int k = 2; k <= CPAD; k <<= 1) {
        for (int j = k >> 1; j > 0; j >>= 1) {
            #pragma unroll
            for (int it = 0; it < CPAD / TK_NT; it++) {
                int t = tid + it * TK_NT;
                int l = t ^ j;
                if (l > t) {
                    float ka = skey[t], kb = skey[l];
                    int   ia = sslot[t], ib = sslot[l];
                    bool asc = ((t & k) == 0);
                    bool beforeBA = (kb > ka) || (kb == ka && ib < ia);
                    if (beforeBA == asc) {
                        skey[t] = kb; skey[l] = ka;
                        sslot[t] = ib; sslot[l] = ia;
                    }
                }
            }
            __syncthreads();
        }
    }

    float* outBoxes  = out;                                     // [4,200,4]
    float* outLabels = out + NIMG * TOPK * 4;                   // [4,200]
    float* outScores = out + NIMG * TOPK * 4 + NIMG * TOPK;     // [4,200]
    float* outCount  = out + NIMG * TOPK * 4 + 2 * NIMG * TOPK; // [4]

    for (int k = tid; k < TOPK; k += TK_NT) {
        float sc = skey[k];
        bool has = (sc != -INFINITY);
        float4 b = make_float4(0.f, 0.f, 0.f, 0.f);
        int lab = 0;
        float scout = 0.f;
        if (has) {
            int slot = sslot[k];
            int c = slot / TOPK, r = slot - c * TOPK;
            b = g_candBox[img][c][r];
            lab = c + 1;
            scout = sc;
        }
        int basei = (img * TOPK + k) * 4;
        outBoxes[basei + 0] = b.x;
        outBoxes[basei + 1] = b.y;
        outBoxes[basei + 2] = b.z;
        outBoxes[basei + 3] = b.w;
        outLabels[img * TOPK + k] = (float)lab;
        outScores[img * TOPK + k] = scout;
    }
    __syncthreads();

    if (tid == 0) {
        int cnt = min(s_total, TOPK);
        if (cnt == 0) {
            int basei = img * TOPK * 4;
            outBoxes[basei + 0] = 0.0f;
            outBoxes[basei + 1] = 0.0f;
            outBoxes[basei + 2] = 1.0f;
            outBoxes[basei + 3] = 1.0f;
            cnt = 1;
        }
        outCount[img] = (float)cnt;
    }
}

// ---------------- launch ----------------
extern "C" void kernel_launch(void* const* d_in, const int* in_sizes, int n_in,
                              void* d_out, int out_size)
{
    const float* locs   = (const float*)d_in[0];  // (4,3106,4)
    const float* scores = (const float*)d_in[1];  // (4,3106,21)
    const float* priors = (const float*)d_in[2];  // (3106,4)
    float* out = (float*)d_out;

    static bool attr_set = false;
    if (!attr_set) {
        cudaFuncSetAttribute(nms_kernel,
                             cudaFuncAttributeMaxDynamicSharedMemorySize,
                             SMEM_NMS_BYTES);
        attr_set = true;
    }

    int rows = NIMG * NPRI;
    softmax_decode_kernel<<<(rows + 127) / 128, 128>>>(locs, scores, priors);
    nms_kernel<<<NIMG * NCLS, NMS_NT, SMEM_NMS_BYTES>>>();
    topk_kernel<<<NIMG, TK_NT>>>(out);
}